// round 16
// baseline (speedup 1.0000x reference)
#include <cuda_runtime.h>

// x: (2,8,4,256,384) fp32 -> 16 independent DxHxW volumes
#define WD   384
#define HT   256
#define DP   4
#define HW   (HT*WD)          // 98304
#define DHW  (DP*HW)          // 393216
#define NIMG 16

#define OUTW   30             // output columns per warp strip (lanes 1..30)
#define NSTRIP 13             // ceil(384/30)
#define CH     8              // output rows per h-chunk
#define NCH    (HT/CH)        // 32
#define NTASK  (NSTRIP*NCH*NIMG)   // 6656 warps, one warp per 32-thread CTA

#define BONUS 10.0f
#define FULL  0xffffffffu

__global__ __launch_bounds__(32)
void cqi_kernel(const float* __restrict__ xg, float* __restrict__ out)
{
    const int gw   = blockIdx.x;                    // one warp per CTA
    const int lane = threadIdx.x;

    const int img   = gw / (NSTRIP * NCH);
    const int rem   = gw - img * (NSTRIP * NCH);
    const int strip = rem % NSTRIP;
    const int hc    = rem / NSTRIP;

    const int w0   = strip * OUTW;
    const int wout = w0 + lane - 1;                 // this lane's output w
    const bool active = (lane >= 1) && (lane <= 30) && (wout < WD);
    int wcol = wout; if (wcol < 0) wcol = 0; if (wcol > WD-1) wcol = WD-1;

    const int h0 = hc * CH;
    const float wf = (float)wout;

    const float* __restrict__ xin = xg + (size_t)img * DHW + wcol;

    // 3-slot rolling row window, slot selected by compile-time (i+k)%3:
    float val[3][4], lf[3][4], rg[3][4], wm[3][4];
    float pend[4];                                  // raw prefetch of next row

    #define LOADROW(HR, DST)                                             \
        do {                                                             \
            const float* _p = xin + (HR) * WD;                           \
            (DST)[0] = __ldg(_p);                                        \
            (DST)[1] = __ldg(_p + HW);                                   \
            (DST)[2] = __ldg(_p + 2*HW);                                 \
            (DST)[3] = __ldg(_p + 3*HW);                                 \
        } while (0)

    // from raw[4] into slot S: shifted copies via shfl; NMS w-max via fmax only
    #define COMMIT(RAW, S)                                               \
        do {                                                             \
            _Pragma("unroll")                                            \
            for (int p = 0; p < 4; ++p) {                                \
                float _v = (RAW)[p];                                     \
                val[S][p] = _v;                                          \
                lf[S][p]  = __shfl_up_sync(FULL, _v, 1);                 \
                rg[S][p]  = __shfl_down_sync(FULL, _v, 1);               \
            }                                                            \
            float _h0 = fmaxf(fmaxf(lf[S][0], val[S][0]), rg[S][0]);     \
            float _h1 = fmaxf(fmaxf(lf[S][1], val[S][1]), rg[S][1]);     \
            float _h2 = fmaxf(fmaxf(lf[S][2], val[S][2]), rg[S][2]);     \
            float _h3 = fmaxf(fmaxf(lf[S][3], val[S][3]), rg[S][3]);     \
            float _m01 = fmaxf(_h0, _h1);                                \
            float _m12 = fmaxf(_h1, _h2);                                \
            float _m23 = fmaxf(_h2, _h3);                                \
            wm[S][0] = _m01;                                             \
            wm[S][1] = fmaxf(_m01, _h2);                                 \
            wm[S][2] = fmaxf(_m12, _h3);                                 \
            wm[S][3] = _m23;                                             \
        } while (0)

    // ---- prologue: rows h0-1 (slot 0) and h0 (slot 1) ----
    {
        float ra[4], rb[4];
        int r_up = h0 - 1; if (r_up < 0) r_up = 0;
        LOADROW(r_up, ra);
        LOADROW(h0,  rb);
        COMMIT(ra, 0);
        COMMIT(rb, 1);
        int r_dn = h0 + 1; if (r_dn > HT-1) r_dn = HT-1;
        LOADROW(r_dn, pend);
    }

    float* __restrict__ oc0 = out + (size_t)img * 3 * DHW;
    float* __restrict__ oy  = out + (size_t)NIMG * 3 * DHW + (size_t)img * DHW;

    const int PA[4] = {0, 0, 1, 2};    // clamped plane d-1
    const int PC[4] = {1, 2, 3, 3};    // clamped plane d+1

    int obase = h0 * WD + wout;

    #pragma unroll
    for (int i = 0; i < CH; ++i) {
        const int h  = h0 + i;
        const int sU = i % 3;           // row h-1
        const int sM = (i + 1) % 3;     // row h
        const int sD = (i + 2) % 3;     // row h+1 (written now)
        const float hf = (float)h;

        // consume prefetch into slot sD, issue next prefetch (row h+2, clamped)
        float tmp[4];
        #pragma unroll
        for (int p = 0; p < 4; ++p) tmp[p] = pend[p];
        int rn = h + 2; if (rn > HT-1) rn = HT-1;
        LOADROW(rn, pend);
        COMMIT(tmp, sD);

        #pragma unroll
        for (int d = 0; d < DP; ++d) {
            const int pa = PA[d], pc = PC[d];
            const float df = (float)d;

            const float xc = val[sM][d];

            const float b0 = 0.5f * (rg[sM][d] - lf[sM][d]);       // dx
            const float b1 = 0.5f * (val[sD][d] - val[sU][d]);     // dy
            const float b2 = 0.5f * (val[sM][pa] - val[sM][pc]);   // ds (flipped)

            const float dxx = rg[sM][d]   - 2.0f*xc + lf[sM][d];
            const float dyy = val[sD][d]  - 2.0f*xc + val[sU][d];
            const float dss = val[sM][pc] - 2.0f*xc + val[sM][pa];
            const float dxy = 0.25f * ( lf[sU][d] - rg[sU][d] - lf[sD][d] + rg[sD][d]);
            const float dys = 0.25f * (-val[sU][pa] + val[sD][pa] + val[sU][pc] - val[sD][pc]);
            const float dxs = 0.25f * (-lf[sM][pa] + rg[sM][pa] + lf[sM][pc] - rg[sM][pc]);

            const float mx = fmaxf(fmaxf(wm[sU][d], wm[sM][d]), wm[sD][d]);
            const bool nms = (xc == mx);

            const float c00 = dyy*dss - dys*dys;
            const float c01 = dxs*dys - dxy*dss;
            const float c02 = dxy*dys - dxs*dyy;
            const float c11 = dxx*dss - dxs*dxs;
            const float c12 = dxy*dxs - dxx*dys;
            const float c22 = dxx*dyy - dxy*dxy;
            const float det = dxx*c00 + dxy*c01 + dxs*c02;

            const bool ok = nms && (det != 0.0f);
            const float invdet = __fdividef(1.0f, (det == 0.0f) ? 1.0f : det);

            const float u0 = (c00*b0 + c01*b1 + c02*b2) * invdet;
            const float u1 = (c01*b0 + c11*b1 + c12*b2) * invdet;
            const float u2 = (c02*b0 + c12*b1 + c22*b2) * invdet;

            float d0 = ok ? -u0 : 0.0f;
            float d1 = ok ? -u1 : 0.0f;
            float d2 = ok ? -u2 : 0.0f;

            const bool small = fmaxf(fmaxf(fabsf(d0), fabsf(d1)), fabsf(d2)) <= 0.7f;
            d0 = small ? d0 : 0.0f;
            d1 = small ? d1 : 0.0f;
            d2 = small ? d2 : 0.0f;

            const float dE = 0.5f * (b0*d0 + b1*d1 + b2*d2);
            const float y  = xc + dE + (ok ? BONUS : 0.0f);

            if (active) {
                const int o = obase + d * HW;
                oc0[o + 0*DHW] = df + d2;
                oc0[o + 1*DHW] = wf + d0;
                oc0[o + 2*DHW] = hf + d1;
                oy [o]         = y;
            }
        }
        obase += WD;
    }
    #undef LOADROW
    #undef COMMIT
}

extern "C" void kernel_launch(void* const* d_in, const int* in_sizes, int n_in,
                              void* d_out, int out_size)
{
    const float* x = (const float*)d_in[0];
    float* out = (float*)d_out;
    dim3 block(32, 1, 1);
    dim3 grid(NTASK, 1, 1);
    cqi_kernel<<<grid, block>>>(x, out);
}

// round 17
// speedup vs baseline: 1.0814x; 1.0814x over previous
#include <cuda_runtime.h>

// x: (2,8,4,256,384) fp32 -> 16 independent DxHxW volumes
#define WD   384
#define HT   256
#define DP   4
#define HW   (HT*WD)          // 98304
#define DHW  (DP*HW)          // 393216
#define NIMG 16

#define OUTW   30             // output columns per warp strip (lanes 1..30)
#define NSTRIP 13             // ceil(384/30)
#define CH     8              // output rows per h-chunk
#define NCH    (HT/CH)        // 32
#define WPB    4              // warps per block
#define NTASK  (NSTRIP*NCH*NIMG)   // 6656 warps

#define BONUS 10.0f
#define FULL  0xffffffffu

// streaming store: evict-first in L2, keeps input resident
__device__ __forceinline__ void stcs(float* p, float v) { __stcs(p, v); }

__global__ __launch_bounds__(128, 6)
void cqi_kernel(const float* __restrict__ xg, float* __restrict__ out)
{
    const int gw   = blockIdx.x * WPB + (threadIdx.x >> 5);
    const int lane = threadIdx.x & 31;

    const int img   = gw / (NSTRIP * NCH);
    const int rem   = gw - img * (NSTRIP * NCH);
    const int strip = rem % NSTRIP;
    const int hc    = rem / NSTRIP;

    const int w0   = strip * OUTW;
    const int wout = w0 + lane - 1;                 // this lane's output w
    const bool active = (lane >= 1) && (lane <= 30) && (wout < WD);
    int wcol = wout; if (wcol < 0) wcol = 0; if (wcol > WD-1) wcol = WD-1;

    const int h0 = hc * CH;
    const float wf = (float)wout;

    const float* __restrict__ xin = xg + (size_t)img * DHW + wcol;

    // 3-slot rolling row window, slot selected by compile-time (i+k)%3:
    float val[3][4], lf[3][4], rg[3][4], wm[3][4];
    float pend[4];                                  // raw prefetch of next row

    #define LOADROW(HR, DST)                                             \
        do {                                                             \
            const float* _p = xin + (HR) * WD;                           \
            (DST)[0] = __ldg(_p);                                        \
            (DST)[1] = __ldg(_p + HW);                                   \
            (DST)[2] = __ldg(_p + 2*HW);                                 \
            (DST)[3] = __ldg(_p + 3*HW);                                 \
        } while (0)

    // from raw[4] into slot S: shifted copies via shfl; NMS w-max via fmax only
    #define COMMIT(RAW, S)                                               \
        do {                                                             \
            _Pragma("unroll")                                            \
            for (int p = 0; p < 4; ++p) {                                \
                float _v = (RAW)[p];                                     \
                val[S][p] = _v;                                          \
                lf[S][p]  = __shfl_up_sync(FULL, _v, 1);                 \
                rg[S][p]  = __shfl_down_sync(FULL, _v, 1);               \
            }                                                            \
            float _h0 = fmaxf(fmaxf(lf[S][0], val[S][0]), rg[S][0]);     \
            float _h1 = fmaxf(fmaxf(lf[S][1], val[S][1]), rg[S][1]);     \
            float _h2 = fmaxf(fmaxf(lf[S][2], val[S][2]), rg[S][2]);     \
            float _h3 = fmaxf(fmaxf(lf[S][3], val[S][3]), rg[S][3]);     \
            float _m01 = fmaxf(_h0, _h1);                                \
            float _m12 = fmaxf(_h1, _h2);                                \
            float _m23 = fmaxf(_h2, _h3);                                \
            wm[S][0] = _m01;                                             \
            wm[S][1] = fmaxf(_m01, _h2);                                 \
            wm[S][2] = fmaxf(_m12, _h3);                                 \
            wm[S][3] = _m23;                                             \
        } while (0)

    // ---- prologue: rows h0-1 (slot 0) and h0 (slot 1) ----
    {
        float ra[4], rb[4];
        int r_up = h0 - 1; if (r_up < 0) r_up = 0;
        LOADROW(r_up, ra);
        LOADROW(h0,  rb);
        COMMIT(ra, 0);
        COMMIT(rb, 1);
        int r_dn = h0 + 1; if (r_dn > HT-1) r_dn = HT-1;
        LOADROW(r_dn, pend);
    }

    float* __restrict__ oc0 = out + (size_t)img * 3 * DHW;
    float* __restrict__ oy  = out + (size_t)NIMG * 3 * DHW + (size_t)img * DHW;

    const int PA[4] = {0, 0, 1, 2};    // clamped plane d-1
    const int PC[4] = {1, 2, 3, 3};    // clamped plane d+1

    int obase = h0 * WD + wout;

    #pragma unroll
    for (int i = 0; i < CH; ++i) {
        const int h  = h0 + i;
        const int sU = i % 3;           // row h-1
        const int sM = (i + 1) % 3;     // row h
        const int sD = (i + 2) % 3;     // row h+1 (written now)
        const float hf = (float)h;

        // consume prefetch into slot sD, issue next prefetch (row h+2, clamped)
        float tmp[4];
        #pragma unroll
        for (int p = 0; p < 4; ++p) tmp[p] = pend[p];
        int rn = h + 2; if (rn > HT-1) rn = HT-1;
        LOADROW(rn, pend);
        COMMIT(tmp, sD);

        #pragma unroll
        for (int d = 0; d < DP; ++d) {
            const int pa = PA[d], pc = PC[d];
            const float df = (float)d;

            const float xc = val[sM][d];

            const float b0 = 0.5f * (rg[sM][d] - lf[sM][d]);       // dx
            const float b1 = 0.5f * (val[sD][d] - val[sU][d]);     // dy
            const float b2 = 0.5f * (val[sM][pa] - val[sM][pc]);   // ds (flipped)

            const float dxx = rg[sM][d]   - 2.0f*xc + lf[sM][d];
            const float dyy = val[sD][d]  - 2.0f*xc + val[sU][d];
            const float dss = val[sM][pc] - 2.0f*xc + val[sM][pa];
            const float dxy = 0.25f * ( lf[sU][d] - rg[sU][d] - lf[sD][d] + rg[sD][d]);
            const float dys = 0.25f * (-val[sU][pa] + val[sD][pa] + val[sU][pc] - val[sD][pc]);
            const float dxs = 0.25f * (-lf[sM][pa] + rg[sM][pa] + lf[sM][pc] - rg[sM][pc]);

            const float mx = fmaxf(fmaxf(wm[sU][d], wm[sM][d]), wm[sD][d]);
            const bool nms = (xc == mx);

            const float c00 = dyy*dss - dys*dys;
            const float c01 = dxs*dys - dxy*dss;
            const float c02 = dxy*dys - dxs*dyy;
            const float c11 = dxx*dss - dxs*dxs;
            const float c12 = dxy*dxs - dxx*dys;
            const float c22 = dxx*dyy - dxy*dxy;
            const float det = dxx*c00 + dxy*c01 + dxs*c02;

            const bool ok = nms && (det != 0.0f);
            const float invdet = __fdividef(1.0f, (det == 0.0f) ? 1.0f : det);

            const float u0 = (c00*b0 + c01*b1 + c02*b2) * invdet;
            const float u1 = (c01*b0 + c11*b1 + c12*b2) * invdet;
            const float u2 = (c02*b0 + c12*b1 + c22*b2) * invdet;

            float d0 = ok ? -u0 : 0.0f;
            float d1 = ok ? -u1 : 0.0f;
            float d2 = ok ? -u2 : 0.0f;

            const bool small = fmaxf(fmaxf(fabsf(d0), fabsf(d1)), fabsf(d2)) <= 0.7f;
            d0 = small ? d0 : 0.0f;
            d1 = small ? d1 : 0.0f;
            d2 = small ? d2 : 0.0f;

            const float dE = 0.5f * (b0*d0 + b1*d1 + b2*d2);
            const float y  = xc + dE + (ok ? BONUS : 0.0f);

            if (active) {
                const int o = obase + d * HW;
                stcs(oc0 + o + 0*DHW, df + d2);
                stcs(oc0 + o + 1*DHW, wf + d0);
                stcs(oc0 + o + 2*DHW, hf + d1);
                stcs(oy  + o,         y);
            }
        }
        obase += WD;
    }
    #undef LOADROW
    #undef COMMIT
}

extern "C" void kernel_launch(void* const* d_in, const int* in_sizes, int n_in,
                              void* d_out, int out_size)
{
    const float* x = (const float*)d_in[0];
    float* out = (float*)d_out;
    dim3 block(WPB * 32, 1, 1);
    dim3 grid(NTASK / WPB, 1, 1);
    cqi_kernel<<<grid, block>>>(x, out);
}